// round 2
// baseline (speedup 1.0000x reference)
#include <cuda_runtime.h>
#include <cuda_bf16.h>

// ---------------- problem constants ----------------
#define S_LEN   256
#define HID     2048
#define NK      4
#define NV      32
#define DK      128
#define DV      128
#define KEY_DIM 512          // NK*DK
#define VAL_DIM 4096         // NV*DV
#define CONV_DIM 5120        // 2*KEY_DIM + VAL_DIM
#define QKVZ_DIM 9216        // 2*KEY_DIM + 2*VAL_DIM
#define Q_SCALE 0.08838834764831845f   // DK^-0.5
#define EPS 1e-6f

typedef unsigned long long u64;

// ---------------- scratch (static device memory, allowed) ----------------
__device__ float g_qkvz[S_LEN * QKVZ_DIM];      // 9.4 MB
__device__ float g_ba  [S_LEN * 64];
__device__ float g_conv[S_LEN * CONV_DIM];      // 5.2 MB
__device__ float g_Qr  [NV * S_LEN * DK];       // [h][s][d] (repeated heads, pre-scaled)
__device__ float g_Kr  [NV * S_LEN * DK];       // [h][s][d]
__device__ float g_Vbt [NV * DV * S_LEN];       // [h][d][s]  (v * beta, transposed)
__device__ float g_S   [NV * S_LEN * S_LEN];    // [h][s][t]  masked scores
__device__ float g_attn[S_LEN * VAL_DIM];       // [s][h*128+d]
__device__ float g_part[4 * S_LEN * HID];       // out_proj K-split partials

// ---------------- f32x2 helpers ----------------
__device__ __forceinline__ u64 pack_dup(float x) {
    u64 r;
    asm("mov.b64 %0, {%1, %1};" : "=l"(r) : "f"(x));
    return r;
}
__device__ __forceinline__ void ffma2(u64& c, u64 a, u64 b) {
    asm("fma.rn.f32x2 %0, %1, %2, %0;" : "+l"(c) : "l"(a), "l"(b));
}
__device__ __forceinline__ float2 unpack2(u64 v) {
    float2 r;
    asm("mov.b64 {%0, %1}, %2;" : "=f"(r.x), "=f"(r.y) : "l"(v));
    return r;
}

// ---------------- generalized strided-batched SGEMM: C = A * B^T ----------------
// A: [M,K] row-major (lda), B: [N,K] row-major (ldb), C: [M,N] row-major (ldc).
// blockIdx.z: either batch index (advance by sA/sB/sC) or K-split index
// (ksplit>1: sA=sB=0, C advances by sC per split, K range is the z-th chunk).
// Tile 128x128x16, 256 threads, 8x8 micro-tile on packed f32x2 FFMA.
__global__ void __launch_bounds__(256)
sgemm_f32x2(const float* __restrict__ A, int lda, int sA,
            const float* __restrict__ B, int ldb, int sB,
            float* __restrict__ C, int ldc, int sC,
            int K, int causal, int ksplit)
{
    __shared__ float As[16][132];
    __shared__ float Bs[16][132];

    const int z = blockIdx.z;
    int k0beg = 0, kLen = K;
    if (ksplit > 1) { kLen = K / ksplit; k0beg = z * kLen; }
    A += (size_t)z * sA;
    B += (size_t)z * sB;
    C += (size_t)z * sC;

    const int tid = threadIdx.x;
    const int lr = tid >> 2;          // 0..63 load row
    const int lc = tid & 3;           // float4 chunk within BK=16
    const int bm = blockIdx.x * 128;
    const int bn = blockIdx.y * 128;

    const float* Ag0 = A + (size_t)(bm + lr)      * lda + k0beg + lc * 4;
    const float* Ag1 = A + (size_t)(bm + lr + 64) * lda + k0beg + lc * 4;
    const float* Bg0 = B + (size_t)(bn + lr)      * ldb + k0beg + lc * 4;
    const float* Bg1 = B + (size_t)(bn + lr + 64) * ldb + k0beg + lc * 4;

    const int ty = tid >> 4;          // 0..15 -> rows ty*8
    const int tx = tid & 15;          // 0..15 -> cols tx*8

    u64 acc[8][4];
#pragma unroll
    for (int i = 0; i < 8; i++)
#pragma unroll
        for (int j = 0; j < 4; j++) acc[i][j] = 0ULL;

    for (int kk0 = 0; kk0 < kLen; kk0 += 16) {
        float4 a0 = *(const float4*)(Ag0 + kk0);
        float4 a1 = *(const float4*)(Ag1 + kk0);
        float4 b0 = *(const float4*)(Bg0 + kk0);
        float4 b1 = *(const float4*)(Bg1 + kk0);
        const int kb = lc * 4;
        As[kb+0][lr] = a0.x; As[kb+1][lr] = a0.y; As[kb+2][lr] = a0.z; As[kb+3][lr] = a0.w;
        As[kb+0][lr+64] = a1.x; As[kb+1][lr+64] = a1.y; As[kb+2][lr+64] = a1.z; As[kb+3][lr+64] = a1.w;
        Bs[kb+0][lr] = b0.x; Bs[kb+1][lr] = b0.y; Bs[kb+2][lr] = b0.z; Bs[kb+3][lr] = b0.w;
        Bs[kb+0][lr+64] = b1.x; Bs[kb+1][lr+64] = b1.y; Bs[kb+2][lr+64] = b1.z; Bs[kb+3][lr+64] = b1.w;
        __syncthreads();

#pragma unroll
        for (int kk = 0; kk < 16; kk++) {
            float4 af0 = *(const float4*)&As[kk][ty * 8];
            float4 af1 = *(const float4*)&As[kk][ty * 8 + 4];
            double2 bd0 = *(const double2*)&Bs[kk][tx * 8];
            double2 bd1 = *(const double2*)&Bs[kk][tx * 8 + 4];
            u64 b[4];
            b[0] = __double_as_longlong(bd0.x);
            b[1] = __double_as_longlong(bd0.y);
            b[2] = __double_as_longlong(bd1.x);
            b[3] = __double_as_longlong(bd1.y);
            u64 a2[8];
            a2[0] = pack_dup(af0.x); a2[1] = pack_dup(af0.y);
            a2[2] = pack_dup(af0.z); a2[3] = pack_dup(af0.w);
            a2[4] = pack_dup(af1.x); a2[5] = pack_dup(af1.y);
            a2[6] = pack_dup(af1.z); a2[7] = pack_dup(af1.w);
#pragma unroll
            for (int i = 0; i < 8; i++)
#pragma unroll
                for (int j = 0; j < 4; j++)
                    ffma2(acc[i][j], a2[i], b[j]);
        }
        __syncthreads();
    }

    // epilogue
#pragma unroll
    for (int i = 0; i < 8; i++) {
        const int grow = bm + ty * 8 + i;
        float* crow = C + (size_t)grow * ldc + bn + tx * 8;
        float2 p0 = unpack2(acc[i][0]);
        float2 p1 = unpack2(acc[i][1]);
        float2 p2 = unpack2(acc[i][2]);
        float2 p3 = unpack2(acc[i][3]);
        if (causal) {
            const int gc = bn + tx * 8;
            if (gc + 0 > grow) p0.x = 0.f;
            if (gc + 1 > grow) p0.y = 0.f;
            if (gc + 2 > grow) p1.x = 0.f;
            if (gc + 3 > grow) p1.y = 0.f;
            if (gc + 4 > grow) p2.x = 0.f;
            if (gc + 5 > grow) p2.y = 0.f;
            if (gc + 6 > grow) p3.x = 0.f;
            if (gc + 7 > grow) p3.y = 0.f;
        }
        float4 o0 = make_float4(p0.x, p0.y, p1.x, p1.y);
        float4 o1 = make_float4(p2.x, p2.y, p3.x, p3.y);
        *(float4*)crow = o0;
        *(float4*)(crow + 4) = o1;
    }
}

// ---------------- ba = hs @ w_ba^T  (N=64, tiny) ----------------
__global__ void ba_gemm(const float* __restrict__ hs, const float* __restrict__ w,
                        float* __restrict__ ba)
{
    const int s = blockIdx.x;
    const int t = threadIdx.x;
    const int n = t & 63, kc = t >> 6;   // 4 K-chunks of 512
    const float4* a = (const float4*)(hs + (size_t)s * HID + kc * 512);
    const float4* b = (const float4*)(w + (size_t)n * HID + kc * 512);
    float acc = 0.f;
#pragma unroll 8
    for (int i = 0; i < 128; i++) {
        float4 x = a[i], y = b[i];
        acc += x.x * y.x + x.y * y.y + x.z * y.z + x.w * y.w;
    }
    __shared__ float red[256];
    red[t] = acc;
    __syncthreads();
    if (t < 64)
        ba[s * 64 + n] = red[n] + red[n + 64] + red[n + 128] + red[n + 192];
}

// ---------------- causal depthwise conv (K=4) + SiLU ----------------
__global__ void conv_silu(const float* __restrict__ qkvz, const float* __restrict__ cw,
                          float* __restrict__ out)
{
    const int c = blockIdx.x * 256 + threadIdx.x;   // 0..5119
    const int s = blockIdx.y;                       // 0..255
    const float4 w = ((const float4*)cw)[c];        // w0..w3
    const float* col = qkvz + c;
    float acc = w.w * col[(size_t)s * QKVZ_DIM];
    if (s >= 1) acc += w.z * col[(size_t)(s - 1) * QKVZ_DIM];
    if (s >= 2) acc += w.y * col[(size_t)(s - 2) * QKVZ_DIM];
    if (s >= 3) acc += w.x * col[(size_t)(s - 3) * QKVZ_DIM];
    out[(size_t)s * CONV_DIM + c] = acc / (1.f + expf(-acc));
}

// ---------------- head prep: Qr (scaled, repeated), Kr, Vbt (=v*beta, transposed) ----
__global__ void prep_kernel(const float* __restrict__ conv, const float* __restrict__ ba,
                            const float* __restrict__ dt_bias,
                            float* __restrict__ Qr, float* __restrict__ Kr,
                            float* __restrict__ Vbt)
{
    const int idx = blockIdx.x * 256 + threadIdx.x;  // < 32*256*128
    const int sec = blockIdx.y;
    if (sec == 0) {
        int h = idx >> 15, s = (idx >> 7) & 255, d = idx & 127;
        Qr[idx] = conv[(size_t)s * CONV_DIM + ((h >> 3) << 7) + d] * Q_SCALE;
    } else if (sec == 1) {
        int h = idx >> 15, s = (idx >> 7) & 255, d = idx & 127;
        Kr[idx] = conv[(size_t)s * CONV_DIM + KEY_DIM + ((h >> 3) << 7) + d];
    } else {
        int h = idx >> 15, d = (idx >> 8) & 127, s = idx & 255;
        float b = ba[s * 64 + h] + dt_bias[h];
        float beta = 1.f / (1.f + expf(-b));
        Vbt[idx] = conv[(size_t)s * CONV_DIM + 2 * KEY_DIM + (h << 7) + d] * beta;
    }
}

// ---------------- gated RMSNorm (in-place on g_attn) ----------------
__global__ void rmsnorm_gate(float* __restrict__ attn, const float* __restrict__ qkvz,
                             const float* __restrict__ norm_w)
{
    const int s = blockIdx.x >> 5, h = blockIdx.x & 31, d = threadIdx.x;
    const int oi = (s << 12) + (h << 7) + d;
    float o = attn[oi];
    float sq = o * o;
#pragma unroll
    for (int off = 16; off; off >>= 1) sq += __shfl_xor_sync(0xffffffffu, sq, off);
    __shared__ float wsum[4];
    if ((d & 31) == 0) wsum[d >> 5] = sq;
    __syncthreads();
    float var = (wsum[0] + wsum[1] + wsum[2] + wsum[3]) * (1.f / 128.f);
    float r = rsqrtf(var + EPS);
    float zv = qkvz[(size_t)s * QKVZ_DIM + CONV_DIM + (h << 7) + d];
    float g = zv / (1.f + expf(-zv));
    attn[oi] = o * r * norm_w[d] * g;
}

// ---------------- K-split partial reduction ----------------
__global__ void reduce4(const float* __restrict__ p, float* __restrict__ out)
{
    const int i = blockIdx.x * 256 + threadIdx.x;
    out[i] = p[i] + p[i + S_LEN * HID] + p[i + 2 * S_LEN * HID] + p[i + 3 * S_LEN * HID];
}

// ---------------- launch ----------------
extern "C" void kernel_launch(void* const* d_in, const int* in_sizes, int n_in,
                              void* d_out, int out_size)
{
    const float* hs      = (const float*)d_in[0];  // [256,2048]
    const float* w_qkvz  = (const float*)d_in[1];  // [9216,2048]
    const float* w_ba    = (const float*)d_in[2];  // [64,2048]
    const float* w_out   = (const float*)d_in[3];  // [2048,4096]
    const float* conv_w  = (const float*)d_in[4];  // [5120,1,4]
    const float* dt_bias = (const float*)d_in[5];  // [32]
    // d_in[6] = A_log (dead code in reference)
    const float* norm_w  = (const float*)d_in[7];  // [128]
    float* out = (float*)d_out;

    float *qkvz, *ba, *conv, *Qr, *Kr, *Vbt, *Sb, *attn, *part;
    cudaGetSymbolAddress((void**)&qkvz, g_qkvz);
    cudaGetSymbolAddress((void**)&ba,   g_ba);
    cudaGetSymbolAddress((void**)&conv, g_conv);
    cudaGetSymbolAddress((void**)&Qr,   g_Qr);
    cudaGetSymbolAddress((void**)&Kr,   g_Kr);
    cudaGetSymbolAddress((void**)&Vbt,  g_Vbt);
    cudaGetSymbolAddress((void**)&Sb,   g_S);
    cudaGetSymbolAddress((void**)&attn, g_attn);
    cudaGetSymbolAddress((void**)&part, g_part);

    // 1) qkvz = hs @ w_qkvz^T : [256,9216]
    sgemm_f32x2<<<dim3(2, 72, 1), 256>>>(hs, HID, 0, w_qkvz, HID, 0,
                                         qkvz, QKVZ_DIM, 0, HID, 0, 1);
    // 2) ba = hs @ w_ba^T : [256,64]
    ba_gemm<<<256, 256>>>(hs, w_ba, ba);
    // 3) causal depthwise conv + silu over first 5120 cols
    conv_silu<<<dim3(CONV_DIM / 256, S_LEN), 256>>>(qkvz, conv_w, conv);
    // 4) build Qr/Kr (head-repeated) and Vbt (v*beta, [h][d][s])
    prep_kernel<<<dim3(4096, 3), 256>>>(conv, ba, dt_bias, Qr, Kr, Vbt);
    // 5) S = tril(Q K^T) per head : 32 x [256,256]
    sgemm_f32x2<<<dim3(2, 2, NV), 256>>>(Qr, DK, S_LEN * DK, Kr, DK, S_LEN * DK,
                                         Sb, S_LEN, S_LEN * S_LEN, DK, 1, 1);
    // 6) O = S @ (V*beta) per head -> g_attn [s][h*128+d]
    sgemm_f32x2<<<dim3(2, 1, NV), 256>>>(Sb, S_LEN, S_LEN * S_LEN, Vbt, S_LEN, DV * S_LEN,
                                         attn, VAL_DIM, DV, S_LEN, 0, 1);
    // 7) gated RMSNorm in place
    rmsnorm_gate<<<S_LEN * NV, 128>>>(attn, qkvz, norm_w);
    // 8) out_proj with K-split 4 -> partials
    sgemm_f32x2<<<dim3(2, HID / 128, 4), 256>>>(attn, VAL_DIM, 0, w_out, VAL_DIM, 0,
                                                part, HID, S_LEN * HID, VAL_DIM, 0, 4);
    // 9) reduce partials -> d_out
    reduce4<<<S_LEN * HID / 256, 256>>>(part, out);
}

// round 4
// speedup vs baseline: 1.7608x; 1.7608x over previous
#include <cuda_runtime.h>
#include <cuda_bf16.h>
#include <cstdint>

// ---------------- problem constants ----------------
#define S_LEN   256
#define HID     2048
#define NK      4
#define NV      32
#define DK      128
#define DV      128
#define KEY_DIM 512          // NK*DK
#define VAL_DIM 4096         // NV*DV
#define CONV_DIM 5120        // 2*KEY_DIM + VAL_DIM
#define QKVZ_DIM 9216        // 2*KEY_DIM + 2*VAL_DIM
#define Q_SCALE 0.08838834764831845f   // DK^-0.5
#define EPS 1e-6f

typedef unsigned long long u64;
typedef unsigned int u32;

// ---------------- scratch (static device memory, allowed) ----------------
__device__ float g_qkvz[S_LEN * QKVZ_DIM];      // 9.4 MB
__device__ float g_ba  [S_LEN * 64];
__device__ float g_conv[S_LEN * CONV_DIM];      // 5.2 MB
__device__ float g_Qr  [NV * S_LEN * DK];       // [h][s][d] (repeated heads, pre-scaled)
__device__ float g_Kr  [NV * S_LEN * DK];       // [h][s][d]
__device__ float g_Vb  [S_LEN * VAL_DIM];       // [s][h*128+d]  (v * beta, natural layout)
__device__ float g_S   [NV * S_LEN * S_LEN];    // [h][s][t]  masked scores
__device__ float g_attn[S_LEN * VAL_DIM];       // [s][h*128+d]
__device__ float g_part[4 * S_LEN * HID];       // out_proj K-split partials

// ================= low-level helpers =================
__device__ __forceinline__ u32 smem_u32(const void* p) {
    u32 a;
    asm("{ .reg .u64 t; cvta.to.shared.u64 t, %1; cvt.u32.u64 %0, t; }" : "=r"(a) : "l"(p));
    return a;
}
__device__ __forceinline__ void sts128(u32 addr, uint4 v) {
    asm volatile("st.shared.v4.b32 [%0], {%1,%2,%3,%4};"
                 :: "r"(addr), "r"(v.x), "r"(v.y), "r"(v.z), "r"(v.w) : "memory");
}
__device__ __forceinline__ void ldsm4(u32* r, u32 addr) {
    asm volatile("ldmatrix.sync.aligned.m8n8.x4.shared.b16 {%0,%1,%2,%3}, [%4];"
                 : "=r"(r[0]), "=r"(r[1]), "=r"(r[2]), "=r"(r[3]) : "r"(addr));
}
__device__ __forceinline__ void ldsm2(u32* r, u32 addr) {
    asm volatile("ldmatrix.sync.aligned.m8n8.x2.shared.b16 {%0,%1}, [%2];"
                 : "=r"(r[0]), "=r"(r[1]) : "r"(addr));
}
__device__ __forceinline__ void mma_bf16(float* c, const u32* a, const u32* b) {
    asm volatile("mma.sync.aligned.m16n8k16.row.col.f32.bf16.bf16.f32 "
                 "{%0,%1,%2,%3}, {%4,%5,%6,%7}, {%8,%9}, {%0,%1,%2,%3};"
                 : "+f"(c[0]), "+f"(c[1]), "+f"(c[2]), "+f"(c[3])
                 : "r"(a[0]), "r"(a[1]), "r"(a[2]), "r"(a[3]), "r"(b[0]), "r"(b[1]));
}

// split fp32 -> bf16 hi/lo pair (packed 2 per u32)
__device__ __forceinline__ void cvt2(float a, float b, u32& hi, u32& lo) {
    __nv_bfloat16 ha = __float2bfloat16_rn(a), hb = __float2bfloat16_rn(b);
    float ra = a - __bfloat162float(ha), rb = b - __bfloat162float(hb);
    __nv_bfloat16 la = __float2bfloat16_rn(ra), lb = __float2bfloat16_rn(rb);
    u32 bha = (u32)__bfloat16_as_ushort(ha), bhb = (u32)__bfloat16_as_ushort(hb);
    u32 bla = (u32)__bfloat16_as_ushort(la), blb = (u32)__bfloat16_as_ushort(lb);
    hi = bha | (bhb << 16);
    lo = bla | (blb << 16);
}
__device__ __forceinline__ void cvt8(float4 p0, float4 p1, uint4& hi, uint4& lo) {
    cvt2(p0.x, p0.y, hi.x, lo.x);
    cvt2(p0.z, p0.w, hi.y, lo.y);
    cvt2(p1.x, p1.y, hi.z, lo.z);
    cvt2(p1.z, p1.w, hi.w, lo.w);
}

// ================= mma.sync bf16-split GEMM: C = A * B^T =================
// A [M,K] fp32 row-major (lda), B [N,K] fp32 row-major (ldb), C fp32 row-major.
// Tile 128x128, K-chunk 32, double-buffered SMEM holding A/B in bf16 hi+lo.
// 3-pass split: C = Ahi*Bhi + Ahi*Blo + Alo*Bhi  (rel err ~1e-5).
// grid.z = K-split index (partials written to C + z*sC).
// SMEM stage (32KB): Ahi @0, Alo @8192, Bhi @16384, Blo @24576. 2 stages = 64KB.
#define MMA_SMEM_TOTAL 65536

__global__ void __launch_bounds__(256)
gemm_mma(const float* __restrict__ A, int lda,
         const float* __restrict__ B, int ldb,
         float* __restrict__ C, int ldc, int sC,
         int Ktot, int ksplit)
{
    extern __shared__ char smem[];
    const u32 sb = smem_u32(smem);
    const int tid = threadIdx.x;
    const int wid = tid >> 5, lane = tid & 31;
    const int bm = blockIdx.x * 128, bn = blockIdx.y * 128;
    const int kLen = Ktot / ksplit, k0 = blockIdx.z * kLen;
    const int niter = kLen / 32;
    float* Cz = C + (size_t)blockIdx.z * sC;

    // ---- global load mapping: thread -> (row 0..127, 16-float half) ----
    const int grow = tid >> 1;
    const int ghalf = tid & 1;
    const float* Ap = A + (size_t)(bm + grow) * lda + k0 + ghalf * 16;
    const float* Bp = B + (size_t)(bn + grow) * ldb + k0 + ghalf * 16;
    // swizzled smem store offsets for this thread's two 16B chunks
    const int ssw = (grow >> 1) & 3;
    const u32 st0 = (u32)(grow * 64 + (((ghalf * 2 + 0) ^ ssw) * 16));
    const u32 st1 = (u32)(grow * 64 + (((ghalf * 2 + 1) ^ ssw) * 16));

    // ---- warp tile: 2(m) x 4(n), each 64x32 ----
    const int wm = wid & 1, wn = wid >> 1;
    // ldmatrix A: row = wm*64 + mi*16 + (lane&15), chunk = ks*2 + (lane>>4)
    const int arow = wm * 64 + (lane & 15);
    const u32 arow_b = (u32)(arow * 64);
    const int aswz = (arow >> 1) & 3;
    const int ahi = lane >> 4;
    // ldmatrix B: row = wn*32 + nj*8 + (lane&7), chunk = ks*2 + ((lane>>3)&1)
    const int brow = wn * 32 + (lane & 7);
    const u32 brow_b = (u32)(brow * 64);
    const int bswz = (brow >> 1) & 3;
    const int bhi = (lane >> 3) & 1;

    float acc[4][4][4];
#pragma unroll
    for (int i = 0; i < 4; i++)
#pragma unroll
        for (int j = 0; j < 4; j++)
#pragma unroll
            for (int q = 0; q < 4; q++) acc[i][j][q] = 0.f;

    float4 ra[4], rb[4];
#pragma unroll
    for (int j = 0; j < 4; j++) {
        ra[j] = *(const float4*)(Ap + j * 4);
        rb[j] = *(const float4*)(Bp + j * 4);
    }

    for (int it = 0; it < niter; it++) {
        const u32 stg = sb + (u32)((it & 1) * 32768);
        // convert + store current chunk (A hi/lo, B hi/lo)
        {
            uint4 hi, lo;
            cvt8(ra[0], ra[1], hi, lo);
            sts128(stg + st0, hi);
            sts128(stg + 8192 + st0, lo);
            cvt8(ra[2], ra[3], hi, lo);
            sts128(stg + st1, hi);
            sts128(stg + 8192 + st1, lo);
            cvt8(rb[0], rb[1], hi, lo);
            sts128(stg + 16384 + st0, hi);
            sts128(stg + 24576 + st0, lo);
            cvt8(rb[2], rb[3], hi, lo);
            sts128(stg + 16384 + st1, hi);
            sts128(stg + 24576 + st1, lo);
        }
        // prefetch next chunk into registers (overlaps with compute)
        if (it + 1 < niter) {
            const float* a = Ap + (it + 1) * 32;
            const float* b = Bp + (it + 1) * 32;
#pragma unroll
            for (int j = 0; j < 4; j++) {
                ra[j] = *(const float4*)(a + j * 4);
                rb[j] = *(const float4*)(b + j * 4);
            }
        }
        __syncthreads();

#pragma unroll
        for (int ks = 0; ks < 2; ks++) {
            u32 ah[4][4], al[4][4], bh[4][2], bl[4][2];
            const u32 ac = (u32)((((ks * 2 + ahi) ^ aswz)) * 16);
            const u32 abase = stg + arow_b + ac;
#pragma unroll
            for (int mi = 0; mi < 4; mi++) ldsm4(ah[mi], abase + mi * 1024);
#pragma unroll
            for (int mi = 0; mi < 4; mi++) ldsm4(al[mi], abase + 8192 + mi * 1024);
            const u32 bc = (u32)((((ks * 2 + bhi) ^ bswz)) * 16);
            const u32 bbase = stg + 16384 + brow_b + bc;
#pragma unroll
            for (int nj = 0; nj < 4; nj++) ldsm2(bh[nj], bbase + nj * 512);
#pragma unroll
            for (int nj = 0; nj < 4; nj++) ldsm2(bl[nj], bbase + 8192 + nj * 512);
#pragma unroll
            for (int mi = 0; mi < 4; mi++)
#pragma unroll
                for (int nj = 0; nj < 4; nj++) {
                    mma_bf16(acc[mi][nj], ah[mi], bh[nj]);
                    mma_bf16(acc[mi][nj], ah[mi], bl[nj]);
                    mma_bf16(acc[mi][nj], al[mi], bh[nj]);
                }
        }
        __syncthreads();
    }

    // ---- epilogue ----
    const int crow0 = bm + wm * 64 + (lane >> 2);
    const int ccol0 = bn + wn * 32 + (lane & 3) * 2;
#pragma unroll
    for (int mi = 0; mi < 4; mi++)
#pragma unroll
        for (int nj = 0; nj < 4; nj++) {
            const int r = crow0 + mi * 16;
            const int c = ccol0 + nj * 8;
            *(float2*)(Cz + (size_t)r * ldc + c) = make_float2(acc[mi][nj][0], acc[mi][nj][1]);
            *(float2*)(Cz + (size_t)(r + 8) * ldc + c) = make_float2(acc[mi][nj][2], acc[mi][nj][3]);
        }
}

// ---------------- f32x2 helpers ----------------
__device__ __forceinline__ u64 pack_dup(float x) {
    u64 r;
    asm("mov.b64 %0, {%1, %1};" : "=l"(r) : "f"(x));
    return r;
}
__device__ __forceinline__ void ffma2(u64& c, u64 a, u64 b) {
    asm("fma.rn.f32x2 %0, %1, %2, %0;" : "+l"(c) : "l"(a), "l"(b));
}
__device__ __forceinline__ float2 unpack2(u64 v) {
    float2 r;
    asm("mov.b64 {%0, %1}, %2;" : "=f"(r.x), "=f"(r.y) : "l"(v));
    return r;
}

// ---------------- f32x2 SGEMM (attention path) ----------------
// bT=1: C = A * B^T, B [N,K]. bT=0: C = A * B, B [K,N] (ldb = row stride).
__global__ void __launch_bounds__(256)
sgemm_f32x2(const float* __restrict__ A, int lda, int sA,
            const float* __restrict__ B, int ldb, int sB,
            float* __restrict__ C, int ldc, int sC,
            int K, int causal, int bT)
{
    __shared__ __align__(16) float As[16][132];
    __shared__ __align__(16) float Bs[16][132];

    const int z = blockIdx.z;
    A += (size_t)z * sA;
    B += (size_t)z * sB;
    C += (size_t)z * sC;

    const int tid = threadIdx.x;
    const int lr = tid >> 2;
    const int lc = tid & 3;
    const int bm = blockIdx.x * 128;
    const int bn = blockIdx.y * 128;

    const float* Ag0 = A + (size_t)(bm + lr)      * lda + lc * 4;
    const float* Ag1 = A + (size_t)(bm + lr + 64) * lda + lc * 4;
    const float* Bg0 = B + (size_t)(bn + lr)      * ldb + lc * 4;
    const float* Bg1 = B + (size_t)(bn + lr + 64) * ldb + lc * 4;
    // NN-mode mapping
    const int kr = tid >> 4, nc = (tid & 15) * 8;
    const float* Bgn = B + (size_t)kr * ldb + bn + nc;

    const int ty = tid >> 4;
    const int tx = tid & 15;

    u64 acc[8][4];
#pragma unroll
    for (int i = 0; i < 8; i++)
#pragma unroll
        for (int j = 0; j < 4; j++) acc[i][j] = 0ULL;

    for (int kk0 = 0; kk0 < K; kk0 += 16) {
        float4 a0 = *(const float4*)(Ag0 + kk0);
        float4 a1 = *(const float4*)(Ag1 + kk0);
        const int kb = lc * 4;
        As[kb+0][lr] = a0.x; As[kb+1][lr] = a0.y; As[kb+2][lr] = a0.z; As[kb+3][lr] = a0.w;
        As[kb+0][lr+64] = a1.x; As[kb+1][lr+64] = a1.y; As[kb+2][lr+64] = a1.z; As[kb+3][lr+64] = a1.w;
        if (bT) {
            float4 b0 = *(const float4*)(Bg0 + kk0);
            float4 b1 = *(const float4*)(Bg1 + kk0);
            Bs[kb+0][lr] = b0.x; Bs[kb+1][lr] = b0.y; Bs[kb+2][lr] = b0.z; Bs[kb+3][lr] = b0.w;
            Bs[kb+0][lr+64] = b1.x; Bs[kb+1][lr+64] = b1.y; Bs[kb+2][lr+64] = b1.z; Bs[kb+3][lr+64] = b1.w;
        } else {
            float4 b0 = *(const float4*)(Bgn + (size_t)kk0 * ldb);
            float4 b1 = *(const float4*)(Bgn + (size_t)kk0 * ldb + 4);
            *(float4*)&Bs[kr][nc] = b0;
            *(float4*)&Bs[kr][nc + 4] = b1;
        }
        __syncthreads();

#pragma unroll
        for (int kk = 0; kk < 16; kk++) {
            float4 af0 = *(const float4*)&As[kk][ty * 8];
            float4 af1 = *(const float4*)&As[kk][ty * 8 + 4];
            double2 bd0 = *(const double2*)&Bs[kk][tx * 8];
            double2 bd1 = *(const double2*)&Bs[kk][tx * 8 + 4];
            u64 b[4];
            b[0] = __double_as_longlong(bd0.x);
            b[1] = __double_as_longlong(bd0.y);
            b[2] = __double_as_longlong(bd1.x);
            b[3] = __double_as_longlong(bd1.y);
            u64 a2[8];
            a2[0] = pack_dup(af0.x); a2[1] = pack_dup(af0.y);
            a2[2] = pack_dup(af0.z); a2[3] = pack_dup(af0.w);
            a2[4] = pack_dup(af1.x); a2[5] = pack_dup(af1.y);
            a2[6] = pack_dup(af1.z); a2[7] = pack_dup(af1.w);
#pragma unroll
            for (int i = 0; i < 8; i++)
#pragma unroll
                for (int j = 0; j < 4; j++)
                    ffma2(acc[i][j], a2[i], b[j]);
        }
        __syncthreads();
    }

#pragma unroll
    for (int i = 0; i < 8; i++) {
        const int grow = bm + ty * 8 + i;
        float* crow = C + (size_t)grow * ldc + bn + tx * 8;
        float2 p0 = unpack2(acc[i][0]);
        float2 p1 = unpack2(acc[i][1]);
        float2 p2 = unpack2(acc[i][2]);
        float2 p3 = unpack2(acc[i][3]);
        if (causal) {
            const int gc = bn + tx * 8;
            if (gc + 0 > grow) p0.x = 0.f;
            if (gc + 1 > grow) p0.y = 0.f;
            if (gc + 2 > grow) p1.x = 0.f;
            if (gc + 3 > grow) p1.y = 0.f;
            if (gc + 4 > grow) p2.x = 0.f;
            if (gc + 5 > grow) p2.y = 0.f;
            if (gc + 6 > grow) p3.x = 0.f;
            if (gc + 7 > grow) p3.y = 0.f;
        }
        *(float4*)crow = make_float4(p0.x, p0.y, p1.x, p1.y);
        *(float4*)(crow + 4) = make_float4(p2.x, p2.y, p3.x, p3.y);
    }
}

// ---------------- ba = hs @ w_ba^T  (N=64, tiny) ----------------
__global__ void ba_gemm(const float* __restrict__ hs, const float* __restrict__ w,
                        float* __restrict__ ba)
{
    const int s = blockIdx.x;
    const int t = threadIdx.x;
    const int n = t & 63, kc = t >> 6;
    const float4* a = (const float4*)(hs + (size_t)s * HID + kc * 512);
    const float4* b = (const float4*)(w + (size_t)n * HID + kc * 512);
    float acc = 0.f;
#pragma unroll 8
    for (int i = 0; i < 128; i++) {
        float4 x = a[i], y = b[i];
        acc += x.x * y.x + x.y * y.y + x.z * y.z + x.w * y.w;
    }
    __shared__ float red[256];
    red[t] = acc;
    __syncthreads();
    if (t < 64)
        ba[s * 64 + n] = red[n] + red[n + 64] + red[n + 128] + red[n + 192];
}

// ---------------- causal depthwise conv (K=4) + SiLU ----------------
__global__ void conv_silu(const float* __restrict__ qkvz, const float* __restrict__ cw,
                          float* __restrict__ out)
{
    const int c = blockIdx.x * 256 + threadIdx.x;
    const int s = blockIdx.y;
    const float4 w = ((const float4*)cw)[c];
    const float* col = qkvz + c;
    float acc = w.w * col[(size_t)s * QKVZ_DIM];
    if (s >= 1) acc += w.z * col[(size_t)(s - 1) * QKVZ_DIM];
    if (s >= 2) acc += w.y * col[(size_t)(s - 2) * QKVZ_DIM];
    if (s >= 3) acc += w.x * col[(size_t)(s - 3) * QKVZ_DIM];
    out[(size_t)s * CONV_DIM + c] = acc / (1.f + expf(-acc));
}

// ---------------- head prep: Qr (scaled, repeated), Kr, Vb (=v*beta) ----
__global__ void prep_kernel(const float* __restrict__ conv, const float* __restrict__ ba,
                            const float* __restrict__ dt_bias,
                            float* __restrict__ Qr, float* __restrict__ Kr,
                            float* __restrict__ Vb)
{
    const int idx = blockIdx.x * 256 + threadIdx.x;
    const int sec = blockIdx.y;
    if (sec == 0) {
        int h = idx >> 15, s = (idx >> 7) & 255, d = idx & 127;
        Qr[idx] = conv[(size_t)s * CONV_DIM + ((h >> 3) << 7) + d] * Q_SCALE;
    } else if (sec == 1) {
        int h = idx >> 15, s = (idx >> 7) & 255, d = idx & 127;
        Kr[idx] = conv[(size_t)s * CONV_DIM + KEY_DIM + ((h >> 3) << 7) + d];
    } else {
        int s = idx >> 12, h = (idx >> 7) & 31, d = idx & 127;
        float b = ba[s * 64 + h] + dt_bias[h];
        float beta = 1.f / (1.f + expf(-b));
        Vb[idx] = conv[(size_t)s * CONV_DIM + 2 * KEY_DIM + (h << 7) + d] * beta;
    }
}

// ---------------- gated RMSNorm (in-place on g_attn) ----------------
__global__ void rmsnorm_gate(float* __restrict__ attn, const float* __restrict__ qkvz,
                             const float* __restrict__ norm_w)
{
    const int s = blockIdx.x >> 5, h = blockIdx.x & 31, d = threadIdx.x;
    const int oi = (s << 12) + (h << 7) + d;
    float o = attn[oi];
    float sq = o * o;
#pragma unroll
    for (int off = 16; off; off >>= 1) sq += __shfl_xor_sync(0xffffffffu, sq, off);
    __shared__ float wsum[4];
    if ((d & 31) == 0) wsum[d >> 5] = sq;
    __syncthreads();
    float var = (wsum[0] + wsum[1] + wsum[2] + wsum[3]) * (1.f / 128.f);
    float r = rsqrtf(var + EPS);
    float zv = qkvz[(size_t)s * QKVZ_DIM + CONV_DIM + (h << 7) + d];
    float g = zv / (1.f + expf(-zv));
    attn[oi] = o * r * norm_w[d] * g;
}

// ---------------- K-split partial reduction ----------------
__global__ void reduce4(const float* __restrict__ p, float* __restrict__ out)
{
    const int i = blockIdx.x * 256 + threadIdx.x;
    out[i] = p[i] + p[i + S_LEN * HID] + p[i + 2 * S_LEN * HID] + p[i + 3 * S_LEN * HID];
}

// ---------------- launch ----------------
extern "C" void kernel_launch(void* const* d_in, const int* in_sizes, int n_in,
                              void* d_out, int out_size)
{
    const float* hs      = (const float*)d_in[0];  // [256,2048]
    const float* w_qkvz  = (const float*)d_in[1];  // [9216,2048]
    const float* w_ba    = (const float*)d_in[2];  // [64,2048]
    const float* w_out   = (const float*)d_in[3];  // [2048,4096]
    const float* conv_w  = (const float*)d_in[4];  // [5120,1,4]
    const float* dt_bias = (const float*)d_in[5];  // [32]
    const float* norm_w  = (const float*)d_in[7];  // [128]
    float* out = (float*)d_out;

    float *qkvz, *ba, *conv, *Qr, *Kr, *Vb, *Sb, *attn, *part;
    cudaGetSymbolAddress((void**)&qkvz, g_qkvz);
    cudaGetSymbolAddress((void**)&ba,   g_ba);
    cudaGetSymbolAddress((void**)&conv, g_conv);
    cudaGetSymbolAddress((void**)&Qr,   g_Qr);
    cudaGetSymbolAddress((void**)&Kr,   g_Kr);
    cudaGetSymbolAddress((void**)&Vb,   g_Vb);
    cudaGetSymbolAddress((void**)&Sb,   g_S);
    cudaGetSymbolAddress((void**)&attn, g_attn);
    cudaGetSymbolAddress((void**)&part, g_part);

    static int smem_set = 0;
    if (!smem_set) {
        cudaFuncSetAttribute(gemm_mma, cudaFuncAttributeMaxDynamicSharedMemorySize,
                             MMA_SMEM_TOTAL);
        smem_set = 1;
    }

    // 1) qkvz = hs @ w_qkvz^T : [256,9216]   (tensor pipe, bf16 3-pass split)
    gemm_mma<<<dim3(2, 72, 1), 256, MMA_SMEM_TOTAL>>>(hs, HID, w_qkvz, HID,
                                                      qkvz, QKVZ_DIM, 0, HID, 1);
    // 2) ba = hs @ w_ba^T : [256,64]
    ba_gemm<<<256, 256>>>(hs, w_ba, ba);
    // 3) causal depthwise conv + silu over first 5120 cols
    conv_silu<<<dim3(CONV_DIM / 256, S_LEN), 256>>>(qkvz, conv_w, conv);
    // 4) build Qr/Kr (head-repeated) and Vb (v*beta, natural layout)
    prep_kernel<<<dim3(4096, 3), 256>>>(conv, ba, dt_bias, Qr, Kr, Vb);
    // 5) S = tril(Q K^T) per head : 32 x [256,256]
    sgemm_f32x2<<<dim3(2, 2, NV), 256>>>(Qr, DK, S_LEN * DK, Kr, DK, S_LEN * DK,
                                         Sb, S_LEN, S_LEN * S_LEN, DK, 1, 1);
    // 6) O = S @ Vb per head (NN mode) -> g_attn [s][h*128+d]
    sgemm_f32x2<<<dim3(2, 1, NV), 256>>>(Sb, S_LEN, S_LEN * S_LEN, Vb, VAL_DIM, DV,
                                         attn, VAL_DIM, DV, S_LEN, 0, 0);
    // 7) gated RMSNorm in place
    rmsnorm_gate<<<S_LEN * NV, 128>>>(attn, qkvz, norm_w);
    // 8) out_proj (tensor pipe, K-split 4) -> partials
    gemm_mma<<<dim3(2, 16, 4), 256, MMA_SMEM_TOTAL>>>(attn, VAL_DIM, w_out, VAL_DIM,
                                                      part, HID, S_LEN * HID, VAL_DIM, 4);
    // 9) reduce partials -> d_out
    reduce4<<<S_LEN * HID / 256, 256>>>(part, out);
}

// round 5
// speedup vs baseline: 2.2799x; 1.2948x over previous
#include <cuda_runtime.h>
#include <cuda_bf16.h>
#include <cuda_fp16.h>
#include <cstdint>

// ---------------- problem constants ----------------
#define S_LEN   256
#define HID     2048
#define NK      4
#define NV      32
#define DK      128
#define DV      128
#define KEY_DIM 512          // NK*DK
#define VAL_DIM 4096         // NV*DV
#define CONV_DIM 5120        // 2*KEY_DIM + VAL_DIM
#define QKVZ_DIM 9216        // 2*KEY_DIM + 2*VAL_DIM
#define Q_SCALE 0.08838834764831845f   // DK^-0.5
#define EPS 1e-6f

typedef unsigned long long u64;
typedef unsigned int u32;

// ---------------- scratch (static device memory, allowed) ----------------
__device__ float g_qkvz[S_LEN * QKVZ_DIM];      // 9.4 MB
__device__ float g_ba  [S_LEN * 64];
__device__ float g_conv[S_LEN * CONV_DIM];      // 5.2 MB
__device__ float g_Vbt [VAL_DIM * S_LEN];       // [n=h*128+d][t]  (v*beta transposed)
__device__ float g_S   [NK * S_LEN * S_LEN];    // [g][s][t]  4 group score mats (1 MB)
__device__ float g_attn[S_LEN * VAL_DIM];       // [s][h*128+d]
__device__ float g_part[4 * S_LEN * HID];       // out_proj K-split partials

// ================= low-level helpers =================
__device__ __forceinline__ u32 smem_u32(const void* p) {
    u32 a;
    asm("{ .reg .u64 t; cvta.to.shared.u64 t, %1; cvt.u32.u64 %0, t; }" : "=r"(a) : "l"(p));
    return a;
}
__device__ __forceinline__ void sts128(u32 addr, uint4 v) {
    asm volatile("st.shared.v4.b32 [%0], {%1,%2,%3,%4};"
                 :: "r"(addr), "r"(v.x), "r"(v.y), "r"(v.z), "r"(v.w) : "memory");
}
__device__ __forceinline__ void ldsm4(u32* r, u32 addr) {
    asm volatile("ldmatrix.sync.aligned.m8n8.x4.shared.b16 {%0,%1,%2,%3}, [%4];"
                 : "=r"(r[0]), "=r"(r[1]), "=r"(r[2]), "=r"(r[3]) : "r"(addr));
}
__device__ __forceinline__ void ldsm2(u32* r, u32 addr) {
    asm volatile("ldmatrix.sync.aligned.m8n8.x2.shared.b16 {%0,%1}, [%2];"
                 : "=r"(r[0]), "=r"(r[1]) : "r"(addr));
}
__device__ __forceinline__ void mma_f16(float* c, const u32* a, const u32* b) {
    asm volatile("mma.sync.aligned.m16n8k16.row.col.f32.f16.f16.f32 "
                 "{%0,%1,%2,%3}, {%4,%5,%6,%7}, {%8,%9}, {%0,%1,%2,%3};"
                 : "+f"(c[0]), "+f"(c[1]), "+f"(c[2]), "+f"(c[3])
                 : "r"(a[0]), "r"(a[1]), "r"(a[2]), "r"(a[3]), "r"(b[0]), "r"(b[1]));
}

__device__ __forceinline__ u32 packh(__half a, __half b) {
    __half2 h = __halves2half2(a, b);
    return *(u32*)&h;
}
// fp32 -> fp16 hi + fp16 lo (2-way split), 2 values packed per u32
__device__ __forceinline__ void cvt2s(float a, float b, u32& hi, u32& lo) {
    __half ha = __float2half_rn(a), hb = __float2half_rn(b);
    float ra = a - __half2float(ha), rb = b - __half2float(hb);
    hi = packh(ha, hb);
    lo = packh(__float2half_rn(ra), __float2half_rn(rb));
}
__device__ __forceinline__ void cvt8s(float4 p0, float4 p1, uint4& hi, uint4& lo) {
    cvt2s(p0.x, p0.y, hi.x, lo.x);
    cvt2s(p0.z, p0.w, hi.y, lo.y);
    cvt2s(p1.x, p1.y, hi.z, lo.z);
    cvt2s(p1.z, p1.w, hi.w, lo.w);
}
// fp32 -> fp16 single (for B operand)
__device__ __forceinline__ uint4 cvt8h(float4 p0, float4 p1) {
    uint4 r;
    __half2 h0 = __floats2half2_rn(p0.x, p0.y);
    __half2 h1 = __floats2half2_rn(p0.z, p0.w);
    __half2 h2 = __floats2half2_rn(p1.x, p1.y);
    __half2 h3 = __floats2half2_rn(p1.z, p1.w);
    r.x = *(u32*)&h0; r.y = *(u32*)&h1; r.z = *(u32*)&h2; r.w = *(u32*)&h3;
    return r;
}

// ================= mma.sync fp16 2-pass GEMM: C = A * B^T =================
// A [M,K] fp32 row-major (lda), B [N,K] fp32 row-major (ldb), C fp32 row-major.
// Tile 128x128, K-chunk 32, double-buffered SMEM: Ahi/Alo (fp16 split) + B (fp16).
// C = Ahi*B + Alo*B   (rel err ~2^-12 per GEMM).
// z-dim: ksplit>1 -> K-split (k0 = z*K/ksplit, C += z*zC);
//        else batch mode (A += z*zA, B += z*zB, C += z*zC).
// SMEM stage (24KB): Ahi @0, Alo @8192, B @16384. 2 stages = 48KB.
#define MMA_SMEM_TOTAL 49152

__global__ void __launch_bounds__(256)
gemm_mma(const float* __restrict__ A, int lda, int zA,
         const float* __restrict__ B, int ldb, int zB,
         float* __restrict__ C, int ldc, int zC,
         int Ktot, int ksplit, int causal, float scale)
{
    extern __shared__ char smem[];
    const u32 sb = smem_u32(smem);
    const int tid = threadIdx.x;
    const int wid = tid >> 5, lane = tid & 31;
    const int bm = blockIdx.x * 128, bn = blockIdx.y * 128;
    const int z = blockIdx.z;

    int kLen = Ktot, k0 = 0;
    if (ksplit > 1) {
        kLen = Ktot / ksplit;
        k0 = z * kLen;
        C += (size_t)z * zC;
    } else {
        A += (size_t)z * zA;
        B += (size_t)z * zB;
        C += (size_t)z * zC;
    }
    const int niter = kLen / 32;

    // ---- global load mapping: thread -> (row 0..127, 16-float half) ----
    const int grow = tid >> 1;
    const int ghalf = tid & 1;
    const float* Ap = A + (size_t)(bm + grow) * lda + k0 + ghalf * 16;
    const float* Bp = B + (size_t)(bn + grow) * ldb + k0 + ghalf * 16;
    const int ssw = (grow >> 1) & 3;
    const u32 st0 = (u32)(grow * 64 + (((ghalf * 2 + 0) ^ ssw) * 16));
    const u32 st1 = (u32)(grow * 64 + (((ghalf * 2 + 1) ^ ssw) * 16));

    // ---- warp tile: 2(m) x 4(n), each 64x32 ----
    const int wm = wid & 1, wn = wid >> 1;
    const int arow = wm * 64 + (lane & 15);
    const u32 arow_b = (u32)(arow * 64);
    const int aswz = (arow >> 1) & 3;
    const int ahi = lane >> 4;
    const int brow = wn * 32 + (lane & 7);
    const u32 brow_b = (u32)(brow * 64);
    const int bswz = (brow >> 1) & 3;
    const int bhi = (lane >> 3) & 1;

    float acc[4][4][4];
#pragma unroll
    for (int i = 0; i < 4; i++)
#pragma unroll
        for (int j = 0; j < 4; j++)
#pragma unroll
            for (int q = 0; q < 4; q++) acc[i][j][q] = 0.f;

    float4 ra[4], rb[4];
#pragma unroll
    for (int j = 0; j < 4; j++) {
        ra[j] = *(const float4*)(Ap + j * 4);
        rb[j] = *(const float4*)(Bp + j * 4);
    }

    for (int it = 0; it < niter; it++) {
        const u32 stg = sb + (u32)((it & 1) * 24576);
        // convert + store current chunk (A hi/lo split, B single fp16)
        {
            uint4 hi, lo;
            cvt8s(ra[0], ra[1], hi, lo);
            sts128(stg + st0, hi);
            sts128(stg + 8192 + st0, lo);
            cvt8s(ra[2], ra[3], hi, lo);
            sts128(stg + st1, hi);
            sts128(stg + 8192 + st1, lo);
            sts128(stg + 16384 + st0, cvt8h(rb[0], rb[1]));
            sts128(stg + 16384 + st1, cvt8h(rb[2], rb[3]));
        }
        // prefetch next chunk into registers (overlaps with compute)
        if (it + 1 < niter) {
            const float* a = Ap + (it + 1) * 32;
            const float* b = Bp + (it + 1) * 32;
#pragma unroll
            for (int j = 0; j < 4; j++) {
                ra[j] = *(const float4*)(a + j * 4);
                rb[j] = *(const float4*)(b + j * 4);
            }
        }
        __syncthreads();

#pragma unroll
        for (int ks = 0; ks < 2; ks++) {
            u32 ah[4][4], al[4][4], bh[4][2];
            const u32 ac = (u32)((((ks * 2 + ahi) ^ aswz)) * 16);
            const u32 abase = stg + arow_b + ac;
#pragma unroll
            for (int mi = 0; mi < 4; mi++) ldsm4(ah[mi], abase + mi * 1024);
#pragma unroll
            for (int mi = 0; mi < 4; mi++) ldsm4(al[mi], abase + 8192 + mi * 1024);
            const u32 bc = (u32)((((ks * 2 + bhi) ^ bswz)) * 16);
            const u32 bbase = stg + 16384 + brow_b + bc;
#pragma unroll
            for (int nj = 0; nj < 4; nj++) ldsm2(bh[nj], bbase + nj * 512);
#pragma unroll
            for (int mi = 0; mi < 4; mi++)
#pragma unroll
                for (int nj = 0; nj < 4; nj++) {
                    mma_f16(acc[mi][nj], ah[mi], bh[nj]);
                    mma_f16(acc[mi][nj], al[mi], bh[nj]);
                }
        }
        __syncthreads();
    }

    // ---- epilogue (scale + optional causal mask: zero where col > row) ----
    const int crow0 = bm + wm * 64 + (lane >> 2);
    const int ccol0 = bn + wn * 32 + (lane & 3) * 2;
#pragma unroll
    for (int mi = 0; mi < 4; mi++)
#pragma unroll
        for (int nj = 0; nj < 4; nj++) {
            const int r = crow0 + mi * 16;
            const int c = ccol0 + nj * 8;
            float v0 = acc[mi][nj][0] * scale;
            float v1 = acc[mi][nj][1] * scale;
            float v2 = acc[mi][nj][2] * scale;
            float v3 = acc[mi][nj][3] * scale;
            if (causal) {
                if (c     > r)     v0 = 0.f;
                if (c + 1 > r)     v1 = 0.f;
                if (c     > r + 8) v2 = 0.f;
                if (c + 1 > r + 8) v3 = 0.f;
            }
            *(float2*)(C + (size_t)r * ldc + c) = make_float2(v0, v1);
            *(float2*)(C + (size_t)(r + 8) * ldc + c) = make_float2(v2, v3);
        }
}

// ---------------- ba = hs @ w_ba^T  (N=64, tiny) ----------------
__global__ void ba_gemm(const float* __restrict__ hs, const float* __restrict__ w,
                        float* __restrict__ ba)
{
    const int s = blockIdx.x;
    const int t = threadIdx.x;
    const int n = t & 63, kc = t >> 6;
    const float4* a = (const float4*)(hs + (size_t)s * HID + kc * 512);
    const float4* b = (const float4*)(w + (size_t)n * HID + kc * 512);
    float acc = 0.f;
#pragma unroll 8
    for (int i = 0; i < 128; i++) {
        float4 x = a[i], y = b[i];
        acc += x.x * y.x + x.y * y.y + x.z * y.z + x.w * y.w;
    }
    __shared__ float red[256];
    red[t] = acc;
    __syncthreads();
    if (t < 64)
        ba[s * 64 + n] = red[n] + red[n + 64] + red[n + 128] + red[n + 192];
}

// ---------------- causal depthwise conv (K=4) + SiLU, sliding window --------
// Each thread owns one channel c, walks 64 sequence positions. grid (20, 4).
__global__ void conv_silu(const float* __restrict__ qkvz, const float* __restrict__ cw,
                          float* __restrict__ out)
{
    const int c = blockIdx.x * 256 + threadIdx.x;   // 0..5119
    const int s0 = blockIdx.y * 64;
    const float4 w = ((const float4*)cw)[c];
    float x0 = 0.f, x1 = 0.f, x2 = 0.f;
    if (s0 >= 1) x2 = qkvz[(size_t)(s0 - 1) * QKVZ_DIM + c];
    if (s0 >= 2) x1 = qkvz[(size_t)(s0 - 2) * QKVZ_DIM + c];
    if (s0 >= 3) x0 = qkvz[(size_t)(s0 - 3) * QKVZ_DIM + c];
#pragma unroll 4
    for (int i = 0; i < 64; i++) {
        const int s = s0 + i;
        float x3 = qkvz[(size_t)s * QKVZ_DIM + c];
        float acc = w.x * x0 + w.y * x1 + w.z * x2 + w.w * x3;
        out[(size_t)s * CONV_DIM + c] = acc / (1.f + expf(-acc));
        x0 = x1; x1 = x2; x2 = x3;
    }
}

// ---------------- Vbt = (v * beta)^T : [n][t], tiled transpose ----------------
__global__ void prep_vbt(const float* __restrict__ conv, const float* __restrict__ ba,
                         const float* __restrict__ dt_bias, float* __restrict__ Vbt)
{
    __shared__ float tile[32][33];
    const int n0 = blockIdx.x * 32, t0 = blockIdx.y * 32;
    const int tx = threadIdx.x, ty = threadIdx.y;   // 32 x 8
#pragma unroll
    for (int j = 0; j < 4; j++) {
        const int t = t0 + ty + j * 8;
        const int n = n0 + tx;
        const int h = n >> 7;
        float b = ba[t * 64 + h] + dt_bias[h];
        float beta = 1.f / (1.f + expf(-b));
        tile[ty + j * 8][tx] = conv[(size_t)t * CONV_DIM + 2 * KEY_DIM + n] * beta;
    }
    __syncthreads();
#pragma unroll
    for (int j = 0; j < 4; j++) {
        const int n = n0 + ty + j * 8;
        const int t = t0 + tx;
        Vbt[(size_t)n * S_LEN + t] = tile[tx][ty + j * 8];
    }
}

// ---------------- gated RMSNorm (in-place on g_attn) ----------------
__global__ void rmsnorm_gate(float* __restrict__ attn, const float* __restrict__ qkvz,
                             const float* __restrict__ norm_w)
{
    const int s = blockIdx.x >> 5, h = blockIdx.x & 31, d = threadIdx.x;
    const int oi = (s << 12) + (h << 7) + d;
    float o = attn[oi];
    float sq = o * o;
#pragma unroll
    for (int off = 16; off; off >>= 1) sq += __shfl_xor_sync(0xffffffffu, sq, off);
    __shared__ float wsum[4];
    if ((d & 31) == 0) wsum[d >> 5] = sq;
    __syncthreads();
    float var = (wsum[0] + wsum[1] + wsum[2] + wsum[3]) * (1.f / 128.f);
    float r = rsqrtf(var + EPS);
    float zv = qkvz[(size_t)s * QKVZ_DIM + CONV_DIM + (h << 7) + d];
    float g = zv / (1.f + expf(-zv));
    attn[oi] = o * r * norm_w[d] * g;
}

// ---------------- K-split partial reduction ----------------
__global__ void reduce4(const float* __restrict__ p, float* __restrict__ out)
{
    const int i = blockIdx.x * 256 + threadIdx.x;
    out[i] = p[i] + p[i + S_LEN * HID] + p[i + 2 * S_LEN * HID] + p[i + 3 * S_LEN * HID];
}

// ---------------- launch ----------------
extern "C" void kernel_launch(void* const* d_in, const int* in_sizes, int n_in,
                              void* d_out, int out_size)
{
    const float* hs      = (const float*)d_in[0];  // [256,2048]
    const float* w_qkvz  = (const float*)d_in[1];  // [9216,2048]
    const float* w_ba    = (const float*)d_in[2];  // [64,2048]
    const float* w_out   = (const float*)d_in[3];  // [2048,4096]
    const float* conv_w  = (const float*)d_in[4];  // [5120,1,4]
    const float* dt_bias = (const float*)d_in[5];  // [32]
    const float* norm_w  = (const float*)d_in[7];  // [128]
    float* out = (float*)d_out;

    float *qkvz, *ba, *conv, *Vbt, *Sb, *attn, *part;
    cudaGetSymbolAddress((void**)&qkvz, g_qkvz);
    cudaGetSymbolAddress((void**)&ba,   g_ba);
    cudaGetSymbolAddress((void**)&conv, g_conv);
    cudaGetSymbolAddress((void**)&Vbt,  g_Vbt);
    cudaGetSymbolAddress((void**)&Sb,   g_S);
    cudaGetSymbolAddress((void**)&attn, g_attn);
    cudaGetSymbolAddress((void**)&part, g_part);

    static int smem_set = 0;
    if (!smem_set) {
        cudaFuncSetAttribute(gemm_mma, cudaFuncAttributeMaxDynamicSharedMemorySize,
                             MMA_SMEM_TOTAL);
        smem_set = 1;
    }

    // 1) qkvz = hs @ w_qkvz^T : [256,9216]
    gemm_mma<<<dim3(2, 72, 1), 256, MMA_SMEM_TOTAL>>>(
        hs, HID, 0, w_qkvz, HID, 0, qkvz, QKVZ_DIM, 0, HID, 1, 0, 1.f);
    // 2) ba = hs @ w_ba^T : [256,64]
    ba_gemm<<<256, 256>>>(hs, w_ba, ba);
    // 3) causal depthwise conv + silu (first 5120 cols of qkvz)
    conv_silu<<<dim3(20, 4), 256>>>(qkvz, conv_w, conv);
    // 4) Vbt transpose with beta gating
    prep_vbt<<<dim3(VAL_DIM / 32, S_LEN / 32), dim3(32, 8)>>>(conv, ba, dt_bias, Vbt);
    // 5) S_g = Q_SCALE * tril(q_g k_g^T) : 4 groups x [256,256], direct from conv
    gemm_mma<<<dim3(2, 2, NK), 256, MMA_SMEM_TOTAL>>>(
        conv, CONV_DIM, DK, conv + KEY_DIM, CONV_DIM, DK,
        Sb, S_LEN, S_LEN * S_LEN, DK, 1, 1, Q_SCALE);
    // 6) O = S_g @ Vbt_g^T : 4 groups x [256, 1024] -> attn [s][h*128+d]
    gemm_mma<<<dim3(2, 8, NK), 256, MMA_SMEM_TOTAL>>>(
        Sb, S_LEN, S_LEN * S_LEN, Vbt, S_LEN, 1024 * S_LEN,
        attn, VAL_DIM, 1024, S_LEN, 1, 0, 1.f);
    // 7) gated RMSNorm in place
    rmsnorm_gate<<<S_LEN * NV, 128>>>(attn, qkvz, norm_w);
    // 8) out_proj (K-split 4) -> partials
    gemm_mma<<<dim3(2, 16, 4), 256, MMA_SMEM_TOTAL>>>(
        attn, VAL_DIM, 0, w_out, VAL_DIM, 0, part, HID, S_LEN * HID,
        VAL_DIM, 4, 0, 1.f);
    // 9) reduce partials -> d_out
    reduce4<<<S_LEN * HID / 256, 256>>>(part, out);
}